// round 9
// baseline (speedup 1.0000x reference)
#include <cuda_runtime.h>
#include <cuda_fp16.h>

#define NROWS 4096
#define DIM 256
#define INV_T 10.0f
#define EXPSC 14.4269504088896340736f  /* 10 * log2(e) */

// persistent device scratch (no allocations allowed)
__device__ __half g_z1[NROWS * DIM];
__device__ __half g_z2[NROWS * DIM];
// 0: rowsum(exp sim12, diag zeroed), 1: colsum(exp sim12, diag zeroed),
// 2: rowsum(exp sim11 masked), 3: rowsum(exp sim22 masked)
__device__ float g_rowsum[4][NROWS];

__device__ __forceinline__ float fast_ex2(float x) {
    float y;
    asm("ex2.approx.f32 %0, %1;" : "=f"(y) : "f"(x));
    return y;
}

// ---------------------------------------------------------------------------
// Kernel 1: L2-normalize rows (eps clamp), fp32->fp16; zero g_rowsum.
// One warp per row.
// ---------------------------------------------------------------------------
__global__ void normalize_kernel(const float* __restrict__ x1,
                                 const float* __restrict__ x2) {
    int gt = blockIdx.x * blockDim.x + threadIdx.x;
    if (gt < 4 * NROWS) (&g_rowsum[0][0])[gt] = 0.0f;

    int gw = gt >> 5;
    int lane = threadIdx.x & 31;
    const float* src;
    __half* dst;
    int row;
    if (gw < NROWS) { src = x1; dst = g_z1; row = gw; }
    else            { src = x2; dst = g_z2; row = gw - NROWS; }

    const float4* p = (const float4*)(src + row * DIM);
    float4 a = p[lane];
    float4 b = p[lane + 32];
    float s = a.x*a.x + a.y*a.y + a.z*a.z + a.w*a.w
            + b.x*b.x + b.y*b.y + b.z*b.z + b.w*b.w;
#pragma unroll
    for (int o = 16; o; o >>= 1) s += __shfl_xor_sync(0xffffffffu, s, o);
    float sc = 1.0f / fmaxf(sqrtf(s), 1e-8f);

    __half2 h0 = __floats2half2_rn(a.x * sc, a.y * sc);
    __half2 h1 = __floats2half2_rn(a.z * sc, a.w * sc);
    __half2 h2 = __floats2half2_rn(b.x * sc, b.y * sc);
    __half2 h3 = __floats2half2_rn(b.z * sc, b.w * sc);
    uint2 u0 = make_uint2(*(unsigned*)&h0, *(unsigned*)&h1);
    uint2 u1 = make_uint2(*(unsigned*)&h2, *(unsigned*)&h3);
    *(uint2*)(dst + row * DIM + lane * 4) = u0;
    *(uint2*)(dst + row * DIM + 128 + lane * 4) = u1;
}

// ---------------------------------------------------------------------------
// Kernel 2: fused tile-GEMM + exp row/col-reduce. 296 CTAs (2/SM), fp16
// in/accumulate. Tile = 128 rows x 32 cols x K=256. Diagonal entries zeroed
// (exact); loss kernel re-adds exp(10*diag12) from an exact fp32 dot.
// SMEM 96KB: A 64KB + double-buffered B 2x16KB -> occupancy 2, so inter-CTA
// concurrency hides epilogue/barrier stalls (4 warps/SMSP).
//   CTA 0..145  : sim12 (z1 x z2^T), 4096 tiles.  row->rs[0], col->rs[1].
//   CTA 146..220: sim11 upper-tri (2112 tiles, pair-ordered stripes).
//   CTA 221..295: sim22 upper-tri.   row->target; col->target by symmetry
//                 (diagonal-block tiles: rowsum only — full block computed).
// ---------------------------------------------------------------------------
#define SWZ(r, c) (((r) << 9) | ((((c) ^ ((r) & 7))) << 4))
#define SMEM_A 0
#define SMEM_B0 65536
#define SMEM_B1 81920
#define SMEM_TOTAL 98304

__device__ __forceinline__ void cp16(unsigned d, const void* s) {
    asm volatile("cp.async.cg.shared.global [%0], [%1], 16;" :: "r"(d), "l"(s));
}
__device__ __forceinline__ void cp_commit() {
    asm volatile("cp.async.commit_group;");
}
template <int n>
__device__ __forceinline__ void cp_wait() {
    asm volatile("cp.async.wait_group %0;" :: "n"(n));
}
__device__ __forceinline__ void ldsm4(unsigned (&r)[4], unsigned addr) {
    asm volatile("ldmatrix.sync.aligned.m8n8.x4.shared.b16 {%0,%1,%2,%3}, [%4];"
                 : "=r"(r[0]), "=r"(r[1]), "=r"(r[2]), "=r"(r[3]) : "r"(addr));
}
__device__ __forceinline__ void mma16816h(unsigned (&d)[2], const unsigned (&a)[4],
                                          unsigned b0, unsigned b1) {
    asm volatile(
        "mma.sync.aligned.m16n8k16.row.col.f16.f16.f16.f16 "
        "{%0,%1}, {%2,%3,%4,%5}, {%6,%7}, {%0,%1};"
        : "+r"(d[0]), "+r"(d[1])
        : "r"(a[0]), "r"(a[1]), "r"(a[2]), "r"(a[3]), "r"(b0), "r"(b1));
}

// B tile: 32 rows x 256 K fp16 = 16KB. 256 threads x 4 cp16.
__device__ __forceinline__ void load_B(unsigned sb, const __half* Bp,
                                       int j, int tid) {
#pragma unroll
    for (int it = 0; it < 4; it++) {
        int idx = tid + it * 256;
        int r = idx >> 5, c = idx & 31;
        cp16(sb + SWZ(r, c), Bp + (j * 32 + r) * DIM + c * 8);
    }
    cp_commit();
}

__global__ void __launch_bounds__(256, 2) simreduce_kernel() {
    extern __shared__ __align__(128) char smem[];
    const unsigned sbase = (unsigned)__cvta_generic_to_shared(smem);
    const unsigned sA = sbase + SMEM_A;
    const unsigned sB[2] = {sbase + SMEM_B0, sbase + SMEM_B1};

    const int tid = threadIdx.x;
    const int bid = blockIdx.x;
    const int wid = tid >> 5;
    const int lane = tid & 31;
    const int warpM = wid & 3;       // 4 warps over 128 M rows
    const int wN    = wid >> 2;      // 2 warps over 32 N cols (16 each)

    // ---- work decode: matrix + global tile range [g0, g1) over 32-col tiles ----
    int matrix, g0, g1;
    if (bid < 146) {
        matrix = 0;
        g0 = (4096 * bid) / 146;
        g1 = (4096 * (bid + 1)) / 146;
    } else if (bid < 221) {
        int c = bid - 146;
        matrix = 1;
        g0 = (2112 * c) / 75;
        g1 = (2112 * (c + 1)) / 75;
    } else {
        int c = bid - 221;
        matrix = 2;
        g0 = (2112 * c) / 75;
        g1 = (2112 * (c + 1)) / 75;
    }

    const __half* Aptr = (matrix == 2) ? g_z2 : g_z1;
    const __half* Bptr = (matrix == 1) ? g_z1 : g_z2;
    const int rowTarget = (matrix == 0) ? 0 : (1 + matrix);
    const int colTarget = (matrix == 0) ? 1 : (1 + matrix);
    const bool symmetric = (matrix != 0);

    const int lrow = lane & 7, quad = lane >> 3;
    int aRow[2];
#pragma unroll
    for (int mi = 0; mi < 2; mi++) aRow[mi] = warpM * 32 + mi * 16 + lrow + (quad & 1) * 8;
    const int aCq = quad >> 1;
    const int bRowBase = wN * 16 + lrow + (quad >> 1) * 8;
    const int bCq = quad & 1;

    const int erow = lane >> 2;        // accumulator row within fragment
    const int ecol = (lane & 3) * 2;   // accumulator col within n8

    int g = g0;
    while (g < g1) {
        // ---- segment decode: stripe + local tile range [j0, j0+len) (32-col j) ----
        int stripe, j0, len;
        if (matrix == 0) {
            stripe = g >> 7;
            j0 = g & 127;
            len = min(g1 - g, 128 - j0);
        } else {
            int P = g / 132, o = g % 132;
            int run1 = 128 - 4 * P;      // stripe P: tiles j = 4P..127
            if (o < run1) {
                stripe = P; j0 = 4 * P + o;
                len = min(g1 - g, run1 - o);
            } else {                      // stripe 31-P: tiles j = 4(31-P)..127
                stripe = 31 - P;
                int oo = o - run1;
                j0 = 4 * (31 - P) + oo;
                len = min(g1 - g, 132 - o);
            }
        }
        const int row0 = stripe * 128;

        __syncthreads();   // everyone done with previous segment's smem

        // stage A stripe (64KB: 16 cp16/thread) + first B tile
#pragma unroll
        for (int it = 0; it < 16; it++) {
            int idx = tid + it * 256;
            int r = idx >> 5, c = idx & 31;
            cp16(sA + SWZ(r, c), Aptr + (row0 + r) * DIM + c * 8);
        }
        cp_commit();
        load_B(sB[0], Bptr, j0, tid);

        float part[4] = {0.f, 0.f, 0.f, 0.f};

        for (int jj = 0; jj < len; jj++) {
            const int j = j0 + jj;
            const int buf = jj & 1;

            cp_wait<0>();
            __syncthreads();   // B[j] (and A on first iter) visible; buf^1 free
            if (jj + 1 < len) load_B(sB[buf ^ 1], Bptr, j + 1, tid);

            const unsigned sBj = sB[buf];
            unsigned acc[2][2][2];
#pragma unroll
            for (int mi = 0; mi < 2; mi++)
#pragma unroll
                for (int ni = 0; ni < 2; ni++) {
                    acc[mi][ni][0] = 0u;
                    acc[mi][ni][1] = 0u;
                }

#pragma unroll
            for (int ks = 0; ks < 16; ks++) {
                unsigned a[2][4];
#pragma unroll
                for (int mi = 0; mi < 2; mi++) {
                    unsigned addr = sA + (aRow[mi] << 9) +
                                    (((2 * ks + aCq) ^ (aRow[mi] & 7)) << 4);
                    ldsm4(a[mi], addr);
                }
                unsigned b[4];
                {
                    unsigned addr = sBj + (bRowBase << 9) +
                                    (((2 * ks + bCq) ^ (bRowBase & 7)) << 4);
                    ldsm4(b, addr);
                }
#pragma unroll
                for (int mi = 0; mi < 2; mi++)
#pragma unroll
                    for (int ni = 0; ni < 2; ni++)
                        mma16816h(acc[mi][ni], a[mi], b[ni * 2], b[ni * 2 + 1]);
            }

            // ---- epilogue: exp(10*sim), diag zeroing, row + col partials ----
            const bool maybeDiag = ((j >> 2) == stripe);   // tile touches diagonal
            // diagonal-block tiles of symmetric matrices: full block computed by
            // rowsums, so colsums would double-count -> skip them there.
            const bool doCol = (!symmetric) || !maybeDiag;

            float colp0[2], colp1[2];
#pragma unroll
            for (int ni = 0; ni < 2; ni++) { colp0[ni] = 0.f; colp1[ni] = 0.f; }

#pragma unroll
            for (int mi = 0; mi < 2; mi++) {
                float s0 = 0.f, s1 = 0.f;
                int rr0 = row0 + warpM * 32 + mi * 16 + erow;   // global rows
                int rr1 = rr0 + 8;
#pragma unroll
                for (int ni = 0; ni < 2; ni++) {
                    float2 f01 = __half22float2(*(__half2*)&acc[mi][ni][0]);
                    float2 f23 = __half22float2(*(__half2*)&acc[mi][ni][1]);
                    float e0 = fast_ex2(f01.x * EXPSC), e1 = fast_ex2(f01.y * EXPSC);
                    float e2 = fast_ex2(f23.x * EXPSC), e3 = fast_ex2(f23.y * EXPSC);
                    if (maybeDiag) {
                        int cc0 = j * 32 + wN * 16 + ni * 8 + ecol;  // global cols
                        int cc1 = cc0 + 1;
                        if (rr0 == cc0) e0 = 0.f;   // zero diagonal (exact);
                        if (rr0 == cc1) e1 = 0.f;   // sim12 diag re-added in loss
                        if (rr1 == cc0) e2 = 0.f;
                        if (rr1 == cc1) e3 = 0.f;
                    }
                    s0 += e0 + e1;
                    s1 += e2 + e3;
                    colp0[ni] += e0 + e2;
                    colp1[ni] += e1 + e3;
                }
                part[mi * 2 + 0] += s0;
                part[mi * 2 + 1] += s1;
            }

            // column partials: xor-shfl over the 8 erow groups, then REDG
            if (doCol) {
                float* ctgt = &g_rowsum[colTarget][j * 32 + wN * 16];
#pragma unroll
                for (int ni = 0; ni < 2; ni++) {
                    float v0 = colp0[ni], v1 = colp1[ni];
#pragma unroll
                    for (int o = 4; o <= 16; o <<= 1) {
                        v0 += __shfl_xor_sync(0xffffffffu, v0, o);
                        v1 += __shfl_xor_sync(0xffffffffu, v1, o);
                    }
                    if (lane < 4) {
                        int col = ni * 8 + lane * 2;
                        atomicAdd(ctgt + col,     v0);
                        atomicAdd(ctgt + col + 1, v1);
                    }
                }
            }
        }

        // flush register row partials for this segment's stripe
#pragma unroll
        for (int k = 0; k < 4; k++) {
            part[k] += __shfl_xor_sync(0xffffffffu, part[k], 1);
            part[k] += __shfl_xor_sync(0xffffffffu, part[k], 2);
        }
        if ((lane & 3) == 0) {
            int r = row0 + warpM * 32 + erow;
            atomicAdd(&g_rowsum[rowTarget][r],      part[0]);
            atomicAdd(&g_rowsum[rowTarget][r + 8],  part[1]);
            atomicAdd(&g_rowsum[rowTarget][r + 16], part[2]);
            atomicAdd(&g_rowsum[rowTarget][r + 24], part[3]);
        }

        g += len;
    }
}

// ---------------------------------------------------------------------------
// Kernel 3: final losses. One warp per row: exact fp32 diag dot, then
// row i    : log(rowsum12[i] + rowsum11m[i] + e^{10 d}) - 10 d
// row N+i  : log(rowsum22m[i] + colsum12[i] + e^{10 d}) - 10 d
// ---------------------------------------------------------------------------
__global__ void loss_kernel(float* __restrict__ out) {
    int w = (blockIdx.x * blockDim.x + threadIdx.x) >> 5;
    int lane = threadIdx.x & 31;
    if (w >= NROWS) return;

    const __half2* p1 = (const __half2*)(g_z1 + w * DIM);
    const __half2* p2 = (const __half2*)(g_z2 + w * DIM);
    float d = 0.f;
#pragma unroll
    for (int i = 0; i < 4; i++) {
        float2 a = __half22float2(p1[lane * 4 + i]);
        float2 b = __half22float2(p2[lane * 4 + i]);
        d += a.x * b.x + a.y * b.y;
    }
#pragma unroll
    for (int o = 16; o; o >>= 1) d += __shfl_xor_sync(0xffffffffu, d, o);

    if (lane == 0) {
        float ed = fast_ex2(d * EXPSC);
        float dl = d * INV_T;
        out[w]         = logf(g_rowsum[0][w] + g_rowsum[2][w] + ed) - dl;
        out[NROWS + w] = logf(g_rowsum[3][w] + g_rowsum[1][w] + ed) - dl;
    }
}

extern "C" void kernel_launch(void* const* d_in, const int* in_sizes, int n_in,
                              void* d_out, int out_size) {
    const float* x1 = (const float*)d_in[0];
    const float* x2 = (const float*)d_in[1];

    normalize_kernel<<<1024, 256>>>(x1, x2);

    cudaFuncSetAttribute(simreduce_kernel,
                         cudaFuncAttributeMaxDynamicSharedMemorySize, SMEM_TOTAL);
    simreduce_kernel<<<296, 256, SMEM_TOTAL>>>();

    loss_kernel<<<512, 256>>>((float*)d_out);
}

// round 10
// speedup vs baseline: 1.1354x; 1.1354x over previous
#include <cuda_runtime.h>
#include <cuda_fp16.h>

#define NROWS 4096
#define DIM 256
#define INV_T 10.0f
#define EXPSC 14.4269504088896340736f  /* 10 * log2(e) */

// persistent device scratch (no allocations allowed)
__device__ __half g_z1[NROWS * DIM];
__device__ __half g_z2[NROWS * DIM];
// 0: rowsum(exp sim12, diag zeroed), 1: colsum(exp sim12, diag zeroed),
// 2: rowsum(exp sim11 masked), 3: rowsum(exp sim22 masked)
__device__ float g_rowsum[4][NROWS];

__device__ __forceinline__ float fast_ex2(float x) {
    float y;
    asm("ex2.approx.f32 %0, %1;" : "=f"(y) : "f"(x));
    return y;
}

// ---------------------------------------------------------------------------
// Kernel 1: L2-normalize rows (eps clamp), fp32->fp16; zero g_rowsum.
// One warp per row.
// ---------------------------------------------------------------------------
__global__ void normalize_kernel(const float* __restrict__ x1,
                                 const float* __restrict__ x2) {
    int gt = blockIdx.x * blockDim.x + threadIdx.x;
    if (gt < 4 * NROWS) (&g_rowsum[0][0])[gt] = 0.0f;

    int gw = gt >> 5;
    int lane = threadIdx.x & 31;
    const float* src;
    __half* dst;
    int row;
    if (gw < NROWS) { src = x1; dst = g_z1; row = gw; }
    else            { src = x2; dst = g_z2; row = gw - NROWS; }

    const float4* p = (const float4*)(src + row * DIM);
    float4 a = p[lane];
    float4 b = p[lane + 32];
    float s = a.x*a.x + a.y*a.y + a.z*a.z + a.w*a.w
            + b.x*b.x + b.y*b.y + b.z*b.z + b.w*b.w;
#pragma unroll
    for (int o = 16; o; o >>= 1) s += __shfl_xor_sync(0xffffffffu, s, o);
    float sc = 1.0f / fmaxf(sqrtf(s), 1e-8f);

    __half2 h0 = __floats2half2_rn(a.x * sc, a.y * sc);
    __half2 h1 = __floats2half2_rn(a.z * sc, a.w * sc);
    __half2 h2 = __floats2half2_rn(b.x * sc, b.y * sc);
    __half2 h3 = __floats2half2_rn(b.z * sc, b.w * sc);
    uint2 u0 = make_uint2(*(unsigned*)&h0, *(unsigned*)&h1);
    uint2 u1 = make_uint2(*(unsigned*)&h2, *(unsigned*)&h3);
    *(uint2*)(dst + row * DIM + lane * 4) = u0;
    *(uint2*)(dst + row * DIM + 128 + lane * 4) = u1;
}

// ---------------------------------------------------------------------------
// Kernel 2: fused tile-GEMM + exp row/col-reduce. 148 CTAs, 2 warp-groups,
// fp16 inputs + fp16 accumulate. K-loop fragments are register double-buffered
// (ldsm for ks+1 issued before mma of ks) to cover LDS latency at occ 1.
// Tile = 128 rows x 64 cols x K=256. Diagonal entries zeroed (exact);
// loss kernel re-adds exp(10*diag12) from an exact fp32 dot.
//   CTA 0..73   : sim12 (z1 x z2^T), 2048 tiles.  row->rs[0], col->rs[1].
//   CTA 74..110 : sim11 upper-tri (1056 tiles, pair-ordered stripes).
//   CTA 111..147: sim22 upper-tri.   row->target; col->target by symmetry
//                 (diagonal-block tiles: rowsum only — full block computed).
// ---------------------------------------------------------------------------
#define SWZ(r, c) (((r) << 9) | ((((c) ^ ((r) & 7))) << 4))
#define SMEM_A 0
#define SMEM_B(grp, buf) (65536 + ((grp) * 2 + (buf)) * 32768)
#define SMEM_TOTAL 196608

__device__ __forceinline__ void cp16(unsigned d, const void* s) {
    asm volatile("cp.async.cg.shared.global [%0], [%1], 16;" :: "r"(d), "l"(s));
}
__device__ __forceinline__ void cp_commit() {
    asm volatile("cp.async.commit_group;");
}
template <int n>
__device__ __forceinline__ void cp_wait() {
    asm volatile("cp.async.wait_group %0;" :: "n"(n));
}
__device__ __forceinline__ void ldsm4(unsigned (&r)[4], unsigned addr) {
    asm volatile("ldmatrix.sync.aligned.m8n8.x4.shared.b16 {%0,%1,%2,%3}, [%4];"
                 : "=r"(r[0]), "=r"(r[1]), "=r"(r[2]), "=r"(r[3]) : "r"(addr));
}
__device__ __forceinline__ void mma16816h(unsigned (&d)[2], const unsigned (&a)[4],
                                          unsigned b0, unsigned b1) {
    asm volatile(
        "mma.sync.aligned.m16n8k16.row.col.f16.f16.f16.f16 "
        "{%0,%1}, {%2,%3,%4,%5}, {%6,%7}, {%0,%1};"
        : "+r"(d[0]), "+r"(d[1])
        : "r"(a[0]), "r"(a[1]), "r"(a[2]), "r"(a[3]), "r"(b0), "r"(b1));
}
__device__ __forceinline__ void bar_group(int g) {
    asm volatile("bar.sync %0, 128;" :: "r"(g + 1) : "memory");
}

// B tile: 64 rows x 256 K fp16 = 32KB. 128 threads x 16 cp16.
__device__ __forceinline__ void load_B(unsigned sb, const __half* Bp,
                                       int j, int gtid) {
#pragma unroll
    for (int it = 0; it < 16; it++) {
        int idx = gtid + it * 128;
        int r = idx >> 5, c = idx & 31;
        cp16(sb + SWZ(r, c), Bp + (j * 64 + r) * DIM + c * 8);
    }
    cp_commit();
}

__global__ void __launch_bounds__(256, 1) simreduce_kernel() {
    extern __shared__ __align__(128) char smem[];
    const unsigned sbase = (unsigned)__cvta_generic_to_shared(smem);
    const unsigned sA = sbase + SMEM_A;

    const int tid = threadIdx.x;
    const int bid = blockIdx.x;
    const int wid = tid >> 5;
    const int lane = tid & 31;
    const int group = wid >> 2;      // 0: warps 0-3, 1: warps 4-7
    const int gtid = tid & 127;
    const int warpM = wid & 3;       // 32 M-rows per warp

    const unsigned sBg[2] = {sbase + SMEM_B(group, 0), sbase + SMEM_B(group, 1)};

    // ---- work decode: matrix + global tile range [g0, g1) over 64-col tiles ----
    int matrix, g0, g1;
    if (bid < 74) {
        matrix = 0;
        g0 = (2048 * bid) / 74;
        g1 = (2048 * (bid + 1)) / 74;
    } else if (bid < 111) {
        int c = bid - 74;
        matrix = 1;
        g0 = (1056 * c) / 37;
        g1 = (1056 * (c + 1)) / 37;
    } else {
        int c = bid - 111;
        matrix = 2;
        g0 = (1056 * c) / 37;
        g1 = (1056 * (c + 1)) / 37;
    }

    const __half* Aptr = (matrix == 2) ? g_z2 : g_z1;
    const __half* Bptr = (matrix == 1) ? g_z1 : g_z2;
    const int rowTarget = (matrix == 0) ? 0 : (1 + matrix);
    const int colTarget = (matrix == 0) ? 1 : (1 + matrix);
    const bool symmetric = (matrix != 0);

    const int lrow = lane & 7, quad = lane >> 3;
    int aRow[2];
#pragma unroll
    for (int mi = 0; mi < 2; mi++) aRow[mi] = warpM * 32 + mi * 16 + lrow + (quad & 1) * 8;
    const int aCq = quad >> 1;
    int bRow[4];
#pragma unroll
    for (int pq = 0; pq < 4; pq++) bRow[pq] = pq * 16 + lrow + (quad >> 1) * 8;
    const int bCq = quad & 1;

    const int erow = lane >> 2;        // accumulator row within fragment
    const int ecol = (lane & 3) * 2;   // accumulator col within n8

    int g = g0;
    while (g < g1) {
        // ---- segment decode: stripe + local tile range [j0, j0+len) (64-col j) ----
        int stripe, j0, len;
        if (matrix == 0) {
            stripe = g >> 6;
            j0 = g & 63;
            len = min(g1 - g, 64 - j0);
        } else {
            int P = g / 66, o = g % 66;
            int run1 = 64 - 2 * P;       // stripe P: tiles j = 2P..63
            if (o < run1) {
                stripe = P; j0 = 2 * P + o;
                len = min(g1 - g, run1 - o);
            } else {                      // stripe 31-P: tiles j = 2(31-P)..63
                stripe = 31 - P;
                int oo = o - run1;
                j0 = 2 * (31 - P) + oo;
                len = min(g1 - g, 66 - o);
            }
        }
        const int row0 = stripe * 128;

        __syncthreads();   // both groups done with previous segment's smem

        // ---- prologue: B_first(group), A (all), B_second(group) ----
        if (group < len) load_B(sBg[0], Bptr, j0 + group, gtid);
        else             cp_commit();                              // c1
#pragma unroll
        for (int it = 0; it < 16; it++) {
            int idx = tid + it * 256;
            int r = idx >> 5, c = idx & 31;
            cp16(sA + SWZ(r, c), Aptr + (row0 + r) * DIM + c * 8);
        }
        cp_commit();                                               // c2 (A)
        if (group + 2 < len) load_B(sBg[1], Bptr, j0 + group + 2, gtid);
        else                 cp_commit();                          // c3
        cp_wait<1>();        // c1 + c2 (own B_first + A portion) complete
        __syncthreads();     // everyone's A portion landed

        float part[4] = {0.f, 0.f, 0.f, 0.f};

        int t = 0;
        for (int jj = group; jj < len; jj += 2, t++) {
            const int j = j0 + jj;
            const unsigned sBj = sBg[t & 1];

            cp_wait<1>();        // current buffer's copies complete (this thread)
            bar_group(group);    // whole group's copies visible

            unsigned acc[2][8][2];
#pragma unroll
            for (int mi = 0; mi < 2; mi++)
#pragma unroll
                for (int ni = 0; ni < 8; ni++) {
                    acc[mi][ni][0] = 0u;
                    acc[mi][ni][1] = 0u;
                }

            // register double-buffered fragments: ldsm(ks+1) before mma(ks)
            unsigned afr[2][2][4];
            unsigned bfr[2][4][4];
#pragma unroll
            for (int mi = 0; mi < 2; mi++) {
                unsigned addr = sA + (aRow[mi] << 9) +
                                ((aCq ^ (aRow[mi] & 7)) << 4);
                ldsm4(afr[0][mi], addr);
            }
#pragma unroll
            for (int pq = 0; pq < 4; pq++) {
                unsigned addr = sBj + (bRow[pq] << 9) +
                                ((bCq ^ (bRow[pq] & 7)) << 4);
                ldsm4(bfr[0][pq], addr);
            }

#pragma unroll
            for (int ks = 0; ks < 16; ks++) {
                const int cur = ks & 1, nxt = cur ^ 1;
                if (ks < 15) {
                    const int kn = ks + 1;
#pragma unroll
                    for (int mi = 0; mi < 2; mi++) {
                        unsigned addr = sA + (aRow[mi] << 9) +
                                        (((2 * kn + aCq) ^ (aRow[mi] & 7)) << 4);
                        ldsm4(afr[nxt][mi], addr);
                    }
#pragma unroll
                    for (int pq = 0; pq < 4; pq++) {
                        unsigned addr = sBj + (bRow[pq] << 9) +
                                        (((2 * kn + bCq) ^ (bRow[pq] & 7)) << 4);
                        ldsm4(bfr[nxt][pq], addr);
                    }
                }
#pragma unroll
                for (int mi = 0; mi < 2; mi++)
#pragma unroll
                    for (int ni = 0; ni < 8; ni++)
                        mma16816h(acc[mi][ni], afr[cur][mi],
                                  bfr[cur][ni >> 1][(ni & 1) * 2],
                                  bfr[cur][ni >> 1][(ni & 1) * 2 + 1]);
            }

            bar_group(group);    // group done reading sBj; safe to refill
            if (jj + 4 < len) load_B(sBg[t & 1], Bptr, j + 4, gtid);
            else              cp_commit();

            // ---- epilogue: exp(10*sim), diag zeroing, row + col partials ----
            const bool maybeDiag = ((j >> 1) == stripe);   // tile touches diagonal
            // diagonal-block tiles of symmetric matrices: full block computed by
            // rowsums, so colsums would double-count -> skip them there.
            const bool doCol = (!symmetric) || !maybeDiag;

            float colp0[8], colp1[8];
#pragma unroll
            for (int ni = 0; ni < 8; ni++) { colp0[ni] = 0.f; colp1[ni] = 0.f; }

#pragma unroll
            for (int mi = 0; mi < 2; mi++) {
                float s0 = 0.f, s1 = 0.f;
                int rr0 = row0 + warpM * 32 + mi * 16 + erow;   // global rows
                int rr1 = rr0 + 8;
#pragma unroll
                for (int ni = 0; ni < 8; ni++) {
                    float2 f01 = __half22float2(*(__half2*)&acc[mi][ni][0]);
                    float2 f23 = __half22float2(*(__half2*)&acc[mi][ni][1]);
                    float e0 = fast_ex2(f01.x * EXPSC), e1 = fast_ex2(f01.y * EXPSC);
                    float e2 = fast_ex2(f23.x * EXPSC), e3 = fast_ex2(f23.y * EXPSC);
                    if (maybeDiag) {
                        int cc0 = j * 64 + ni * 8 + ecol;        // global cols
                        int cc1 = cc0 + 1;
                        if (rr0 == cc0) e0 = 0.f;   // zero diagonal (exact);
                        if (rr0 == cc1) e1 = 0.f;   // sim12 diag re-added in loss
                        if (rr1 == cc0) e2 = 0.f;
                        if (rr1 == cc1) e3 = 0.f;
                    }
                    s0 += e0 + e1;
                    s1 += e2 + e3;
                    colp0[ni] += e0 + e2;
                    colp1[ni] += e1 + e3;
                }
                part[mi * 2 + 0] += s0;
                part[mi * 2 + 1] += s1;
            }

            // column partials: xor-shfl over the 8 erow groups, then REDG
            if (doCol) {
                float* ctgt = &g_rowsum[colTarget][j * 64];
#pragma unroll
                for (int ni = 0; ni < 8; ni++) {
                    float v0 = colp0[ni], v1 = colp1[ni];
#pragma unroll
                    for (int o = 4; o <= 16; o <<= 1) {
                        v0 += __shfl_xor_sync(0xffffffffu, v0, o);
                        v1 += __shfl_xor_sync(0xffffffffu, v1, o);
                    }
                    if (lane < 4) {
                        int col = ni * 8 + lane * 2;
                        atomicAdd(ctgt + col,     v0);
                        atomicAdd(ctgt + col + 1, v1);
                    }
                }
            }
        }

        // flush register row partials for this segment's stripe
#pragma unroll
        for (int k = 0; k < 4; k++) {
            part[k] += __shfl_xor_sync(0xffffffffu, part[k], 1);
            part[k] += __shfl_xor_sync(0xffffffffu, part[k], 2);
        }
        if ((lane & 3) == 0) {
            int r = row0 + warpM * 32 + erow;
            atomicAdd(&g_rowsum[rowTarget][r],      part[0]);
            atomicAdd(&g_rowsum[rowTarget][r + 8],  part[1]);
            atomicAdd(&g_rowsum[rowTarget][r + 16], part[2]);
            atomicAdd(&g_rowsum[rowTarget][r + 24], part[3]);
        }

        g += len;
    }
}

// ---------------------------------------------------------------------------
// Kernel 3: final losses. One warp per row: exact fp32 diag dot, then
// row i    : log(rowsum12[i] + rowsum11m[i] + e^{10 d}) - 10 d
// row N+i  : log(rowsum22m[i] + colsum12[i] + e^{10 d}) - 10 d
// ---------------------------------------------------------------------------
__global__ void loss_kernel(float* __restrict__ out) {
    int w = (blockIdx.x * blockDim.x + threadIdx.x) >> 5;
    int lane = threadIdx.x & 31;
    if (w >= NROWS) return;

    const __half2* p1 = (const __half2*)(g_z1 + w * DIM);
    const __half2* p2 = (const __half2*)(g_z2 + w * DIM);
    float d = 0.f;
#pragma unroll
    for (int i = 0; i < 4; i++) {
        float2 a = __half22float2(p1[lane * 4 + i]);
        float2 b = __half22float2(p2[lane * 4 + i]);
        d += a.x * b.x + a.y * b.y;
    }
#pragma unroll
    for (int o = 16; o; o >>= 1) d += __shfl_xor_sync(0xffffffffu, d, o);

    if (lane == 0) {
        float ed = fast_ex2(d * EXPSC);
        float dl = d * INV_T;
        out[w]         = logf(g_rowsum[0][w] + g_rowsum[2][w] + ed) - dl;
        out[NROWS + w] = logf(g_rowsum[3][w] + g_rowsum[1][w] + ed) - dl;
    }
}

extern "C" void kernel_launch(void* const* d_in, const int* in_sizes, int n_in,
                              void* d_out, int out_size) {
    const float* x1 = (const float*)d_in[0];
    const float* x2 = (const float*)d_in[1];

    normalize_kernel<<<1024, 256>>>(x1, x2);

    cudaFuncSetAttribute(simreduce_kernel,
                         cudaFuncAttributeMaxDynamicSharedMemorySize, SMEM_TOTAL);
    simreduce_kernel<<<148, 256, SMEM_TOTAL>>>();

    loss_kernel<<<512, 256>>>((float*)d_out);
}

// round 11
// speedup vs baseline: 1.1653x; 1.0263x over previous
#include <cuda_runtime.h>
#include <cuda_fp16.h>

#define NROWS 4096
#define DIM 256
#define INV_T 10.0f
#define EXPSC 14.4269504088896340736f  /* 10 * log2(e) */

// persistent device scratch (no allocations allowed)
__device__ __half g_z1[NROWS * DIM];
__device__ __half g_z2[NROWS * DIM];
// 0: rowsum(exp sim12, diag zeroed), 1: colsum(exp sim12, diag zeroed),
// 2: rowsum(exp sim11 masked), 3: rowsum(exp sim22 masked)
__device__ float g_rowsum[4][NROWS];

__device__ __forceinline__ float fast_ex2(float x) {
    float y;
    asm("ex2.approx.f32 %0, %1;" : "=f"(y) : "f"(x));
    return y;
}

// ---------------------------------------------------------------------------
// Kernel 1: L2-normalize rows (eps clamp), fp32->fp16; zero g_rowsum.
// One warp per row.
// ---------------------------------------------------------------------------
__global__ void normalize_kernel(const float* __restrict__ x1,
                                 const float* __restrict__ x2) {
    int gt = blockIdx.x * blockDim.x + threadIdx.x;
    if (gt < 4 * NROWS) (&g_rowsum[0][0])[gt] = 0.0f;

    int gw = gt >> 5;
    int lane = threadIdx.x & 31;
    const float* src;
    __half* dst;
    int row;
    if (gw < NROWS) { src = x1; dst = g_z1; row = gw; }
    else            { src = x2; dst = g_z2; row = gw - NROWS; }

    const float4* p = (const float4*)(src + row * DIM);
    float4 a = p[lane];
    float4 b = p[lane + 32];
    float s = a.x*a.x + a.y*a.y + a.z*a.z + a.w*a.w
            + b.x*b.x + b.y*b.y + b.z*b.z + b.w*b.w;
#pragma unroll
    for (int o = 16; o; o >>= 1) s += __shfl_xor_sync(0xffffffffu, s, o);
    float sc = 1.0f / fmaxf(sqrtf(s), 1e-8f);

    __half2 h0 = __floats2half2_rn(a.x * sc, a.y * sc);
    __half2 h1 = __floats2half2_rn(a.z * sc, a.w * sc);
    __half2 h2 = __floats2half2_rn(b.x * sc, b.y * sc);
    __half2 h3 = __floats2half2_rn(b.z * sc, b.w * sc);
    uint2 u0 = make_uint2(*(unsigned*)&h0, *(unsigned*)&h1);
    uint2 u1 = make_uint2(*(unsigned*)&h2, *(unsigned*)&h3);
    *(uint2*)(dst + row * DIM + lane * 4) = u0;
    *(uint2*)(dst + row * DIM + 128 + lane * 4) = u1;
}

// ---------------------------------------------------------------------------
// Kernel 2: fused tile-GEMM + exp row/col-reduce. 148 CTAs, 2 warp-groups,
// fp16 in/accumulate, 64x64 WARP tiles (2M x 2N per group) to halve smem
// ldsm duplication (smem-BW bound). Group tile = 128 rows x 128 cols x K=256;
// B staged in K-halves (32KB chunks, buffer parity = K-half), double-buffered
// per group. Diagonal zeroed (exact); loss kernel re-adds exp(10*diag12).
//   CTA 0..73   : sim12 (z1 x z2^T), 1024 tiles.  row->rs[0], col->rs[1].
//   CTA 74..110 : sim11 upper-tri (528 tiles, pair-ordered stripes).
//   CTA 111..147: sim22 upper-tri.   row->target; col->target by symmetry
//                 (diagonal tiles: rowsum only — full tile computed).
// ---------------------------------------------------------------------------
#define SWZA(r, c) (((r) << 9) | ((((c) ^ ((r) & 7))) << 4))          /* A: 512B rows */
#define SWZB(r, c) (((r) << 8) | ((((c) ^ ((r) & 7)) & 15) << 4))     /* B: 256B rows */
#define SMEM_A 0
#define SMEM_B(grp, buf) (65536 + ((grp) * 2 + (buf)) * 32768)
#define SMEM_TOTAL 196608

__device__ __forceinline__ void cp16(unsigned d, const void* s) {
    asm volatile("cp.async.cg.shared.global [%0], [%1], 16;" :: "r"(d), "l"(s));
}
__device__ __forceinline__ void cp_commit() {
    asm volatile("cp.async.commit_group;");
}
template <int n>
__device__ __forceinline__ void cp_wait() {
    asm volatile("cp.async.wait_group %0;" :: "n"(n));
}
__device__ __forceinline__ void ldsm4(unsigned (&r)[4], unsigned addr) {
    asm volatile("ldmatrix.sync.aligned.m8n8.x4.shared.b16 {%0,%1,%2,%3}, [%4];"
                 : "=r"(r[0]), "=r"(r[1]), "=r"(r[2]), "=r"(r[3]) : "r"(addr));
}
__device__ __forceinline__ void mma16816h(unsigned (&d)[2], const unsigned (&a)[4],
                                          unsigned b0, unsigned b1) {
    asm volatile(
        "mma.sync.aligned.m16n8k16.row.col.f16.f16.f16.f16 "
        "{%0,%1}, {%2,%3,%4,%5}, {%6,%7}, {%0,%1};"
        : "+r"(d[0]), "+r"(d[1])
        : "r"(a[0]), "r"(a[1]), "r"(a[2]), "r"(a[3]), "r"(b0), "r"(b1));
}
__device__ __forceinline__ void bar_group(int g) {
    asm volatile("bar.sync %0, 128;" :: "r"(g + 1) : "memory");
}

// B chunk: 128 N-rows x 128 K fp16 = 32KB. 128 threads x 16 cp16.
__device__ __forceinline__ void load_chunk(unsigned sb, const __half* Bp,
                                           int j, int khalf, int gtid) {
#pragma unroll
    for (int it = 0; it < 16; it++) {
        int idx = gtid + it * 128;
        int r = idx >> 4, c = idx & 15;
        cp16(sb + SWZB(r, c), Bp + (j * 128 + r) * DIM + khalf * 128 + c * 8);
    }
    cp_commit();
}

__global__ void __launch_bounds__(256, 1) simreduce_kernel() {
    extern __shared__ __align__(128) char smem[];
    const unsigned sbase = (unsigned)__cvta_generic_to_shared(smem);
    const unsigned sA = sbase + SMEM_A;

    const int tid = threadIdx.x;
    const int bid = blockIdx.x;
    const int wid = tid >> 5;
    const int lane = tid & 31;
    const int group = wid >> 2;      // 0: warps 0-3, 1: warps 4-7
    const int gtid = tid & 127;
    const int wig = wid & 3;         // warp-in-group
    const int mhalf = wig & 1;       // 64 M-rows
    const int nhalf = wig >> 1;      // 64 N-cols

    const unsigned sB0 = sbase + SMEM_B(group, 0);
    const unsigned sB1 = sbase + SMEM_B(group, 1);

    // ---- work decode: matrix + global tile range [g0, g1) over 128-col tiles ----
    int matrix, g0, g1;
    if (bid < 74) {
        matrix = 0;
        g0 = (1024 * bid) / 74;
        g1 = (1024 * (bid + 1)) / 74;
    } else if (bid < 111) {
        int c = bid - 74;
        matrix = 1;
        g0 = (528 * c) / 37;
        g1 = (528 * (c + 1)) / 37;
    } else {
        int c = bid - 111;
        matrix = 2;
        g0 = (528 * c) / 37;
        g1 = (528 * (c + 1)) / 37;
    }

    const __half* Aptr = (matrix == 2) ? g_z2 : g_z1;
    const __half* Bptr = (matrix == 1) ? g_z1 : g_z2;
    const int rowTarget = (matrix == 0) ? 0 : (1 + matrix);
    const int colTarget = (matrix == 0) ? 1 : (1 + matrix);
    const bool symmetric = (matrix != 0);

    const int lrow = lane & 7, quad = lane >> 3;
    int aRow[4];
#pragma unroll
    for (int mi = 0; mi < 4; mi++)
        aRow[mi] = mhalf * 64 + mi * 16 + lrow + (quad & 1) * 8;
    const int aCq = quad >> 1;
    int bRow[4];
#pragma unroll
    for (int pq = 0; pq < 4; pq++)
        bRow[pq] = nhalf * 64 + pq * 16 + lrow + (quad >> 1) * 8;
    const int bCq = quad & 1;

    const int erow = lane >> 2;        // accumulator row within fragment
    const int ecol = (lane & 3) * 2;   // accumulator col within n8

    int g = g0;
    while (g < g1) {
        // ---- segment decode: stripe + local tile range [j0, j0+len) ----
        int stripe, j0, len;
        if (matrix == 0) {
            stripe = g >> 5;
            j0 = g & 31;
            len = min(g1 - g, 32 - j0);
        } else {
            int P = g / 33, o = g % 33;
            int run1 = 32 - P;           // stripe P: tiles j = P..31
            if (o < run1) {
                stripe = P; j0 = P + o;
                len = min(g1 - g, run1 - o);
            } else {                      // stripe 31-P: tiles j = 31-P..31
                stripe = 31 - P;
                int oo = o - run1;
                j0 = (31 - P) + oo;
                len = min(g1 - g, 33 - o);
            }
        }
        const int row0 = stripe * 128;
        const int ntg = (len > group) ? ((len - group + 1) >> 1) : 0;

        __syncthreads();   // both groups done with previous segment's smem

        // ---- prologue: B(t0,k0), A, B(t0,k1) ----
        if (ntg > 0) load_chunk(sB0, Bptr, j0 + group, 0, gtid);
        else         cp_commit();                                  // c1
#pragma unroll
        for (int it = 0; it < 16; it++) {
            int idx = tid + it * 256;
            int r = idx >> 5, c = idx & 31;
            cp16(sA + SWZA(r, c), Aptr + (row0 + r) * DIM + c * 8);
        }
        cp_commit();                                               // c2 (A)
        if (ntg > 0) load_chunk(sB1, Bptr, j0 + group, 1, gtid);
        else         cp_commit();                                  // c3
        cp_wait<1>();
        __syncthreads();     // A fully landed (and c1)

        float part[8];
#pragma unroll
        for (int k = 0; k < 8; k++) part[k] = 0.f;

        for (int t = 0; t < ntg; t++) {
            const int j = j0 + group + 2 * t;
            const bool more = (t + 1 < ntg);

            unsigned acc[4][8][2];
#pragma unroll
            for (int mi = 0; mi < 4; mi++)
#pragma unroll
                for (int ni = 0; ni < 8; ni++) {
                    acc[mi][ni][0] = 0u;
                    acc[mi][ni][1] = 0u;
                }

            // ---- two K-half stages ----
#pragma unroll
            for (int kh = 0; kh < 2; kh++) {
                const unsigned sBj = kh ? sB1 : sB0;
                cp_wait<1>();
                bar_group(group);
#pragma unroll
                for (int ks = 0; ks < 8; ks++) {
                    const int ksg = kh * 8 + ks;
                    unsigned a[4][4];
#pragma unroll
                    for (int mi = 0; mi < 4; mi++) {
                        unsigned addr = sA + (aRow[mi] << 9) +
                                        (((2 * ksg + aCq) ^ (aRow[mi] & 7)) << 4);
                        ldsm4(a[mi], addr);
                    }
                    unsigned b[4][4];
#pragma unroll
                    for (int pq = 0; pq < 4; pq++) {
                        unsigned addr = sBj + (bRow[pq] << 8) +
                                        ((((2 * ks + bCq) ^ (bRow[pq] & 7)) & 15) << 4);
                        ldsm4(b[pq], addr);
                    }
#pragma unroll
                    for (int mi = 0; mi < 4; mi++)
#pragma unroll
                        for (int ni = 0; ni < 8; ni++)
                            mma16816h(acc[mi][ni], a[mi],
                                      b[ni >> 1][(ni & 1) * 2],
                                      b[ni >> 1][(ni & 1) * 2 + 1]);
                }
                bar_group(group);    // group done reading this chunk
                if (more) load_chunk(kh ? sB1 : sB0, Bptr, j + 2, kh, gtid);
                else      cp_commit();
            }

            // ---- epilogue: exp(10*sim), diag zeroing, row + col partials ----
            const bool maybeDiag = (j == stripe);
            const bool doCol = (!symmetric) || !maybeDiag;

            float colp0[8], colp1[8];
#pragma unroll
            for (int ni = 0; ni < 8; ni++) { colp0[ni] = 0.f; colp1[ni] = 0.f; }

#pragma unroll
            for (int mi = 0; mi < 4; mi++) {
                float s0 = 0.f, s1 = 0.f;
                int rr0 = row0 + mhalf * 64 + mi * 16 + erow;   // global rows
                int rr1 = rr0 + 8;
#pragma unroll
                for (int ni = 0; ni < 8; ni++) {
                    float2 f01 = __half22float2(*(__half2*)&acc[mi][ni][0]);
                    float2 f23 = __half22float2(*(__half2*)&acc[mi][ni][1]);
                    float e0 = fast_ex2(f01.x * EXPSC), e1 = fast_ex2(f01.y * EXPSC);
                    float e2 = fast_ex2(f23.x * EXPSC), e3 = fast_ex2(f23.y * EXPSC);
                    if (maybeDiag) {
                        int cc0 = j * 128 + nhalf * 64 + ni * 8 + ecol;
                        int cc1 = cc0 + 1;
                        if (rr0 == cc0) e0 = 0.f;   // zero diagonal (exact);
                        if (rr0 == cc1) e1 = 0.f;   // sim12 diag re-added in loss
                        if (rr1 == cc0) e2 = 0.f;
                        if (rr1 == cc1) e3 = 0.f;
                    }
                    s0 += e0 + e1;
                    s1 += e2 + e3;
                    colp0[ni] += e0 + e2;
                    colp1[ni] += e1 + e3;
                }
                part[mi * 2 + 0] += s0;
                part[mi * 2 + 1] += s1;
            }

            // column partials: xor-shfl over the 8 erow groups, then REDG
            if (doCol) {
                float* ctgt = &g_rowsum[colTarget][j * 128 + nhalf * 64];
#pragma unroll
                for (int ni = 0; ni < 8; ni++) {
                    float v0 = colp0[ni], v1 = colp1[ni];
#pragma unroll
                    for (int o = 4; o <= 16; o <<= 1) {
                        v0 += __shfl_xor_sync(0xffffffffu, v0, o);
                        v1 += __shfl_xor_sync(0xffffffffu, v1, o);
                    }
                    if (lane < 4) {
                        int col = ni * 8 + lane * 2;
                        atomicAdd(ctgt + col,     v0);
                        atomicAdd(ctgt + col + 1, v1);
                    }
                }
            }
        }

        // flush register row partials for this segment's stripe
#pragma unroll
        for (int k = 0; k < 8; k++) {
            part[k] += __shfl_xor_sync(0xffffffffu, part[k], 1);
            part[k] += __shfl_xor_sync(0xffffffffu, part[k], 2);
        }
        if ((lane & 3) == 0) {
#pragma unroll
            for (int mi = 0; mi < 4; mi++) {
                int r = row0 + mhalf * 64 + mi * 16 + erow;
                atomicAdd(&g_rowsum[rowTarget][r],     part[mi * 2 + 0]);
                atomicAdd(&g_rowsum[rowTarget][r + 8], part[mi * 2 + 1]);
            }
        }

        g += len;
    }
}

// ---------------------------------------------------------------------------
// Kernel 3: final losses. One warp per row: exact fp32 diag dot, then
// row i    : log(rowsum12[i] + rowsum11m[i] + e^{10 d}) - 10 d
// row N+i  : log(rowsum22m[i] + colsum12[i] + e^{10 d}) - 10 d
// ---------------------------------------------------------------------------
__global__ void loss_kernel(float* __restrict__ out) {
    int w = (blockIdx.x * blockDim.x + threadIdx.x) >> 5;
    int lane = threadIdx.x & 31;
    if (w >= NROWS) return;

    const __half2* p1 = (const __half2*)(g_z1 + w * DIM);
    const __half2* p2 = (const __half2*)(g_z2 + w * DIM);
    float d = 0.f;
#pragma unroll
    for (int i = 0; i < 4; i++) {
        float2 a = __half22float2(p1[lane * 4 + i]);
        float2 b = __half22float2(p2[lane * 4 + i]);
        d += a.x * b.x + a.y * b.y;
    }
#pragma unroll
    for (int o = 16; o; o >>= 1) d += __shfl_xor_sync(0xffffffffu, d, o);

    if (lane == 0) {
        float ed = fast_ex2(d * EXPSC);
        float dl = d * INV_T;
        out[w]         = logf(g_rowsum[0][w] + g_rowsum[2][w] + ed) - dl;
        out[NROWS + w] = logf(g_rowsum[3][w] + g_rowsum[1][w] + ed) - dl;
    }
}

extern "C" void kernel_launch(void* const* d_in, const int* in_sizes, int n_in,
                              void* d_out, int out_size) {
    const float* x1 = (const float*)d_in[0];
    const float* x2 = (const float*)d_in[1];

    normalize_kernel<<<1024, 256>>>(x1, x2);

    cudaFuncSetAttribute(simreduce_kernel,
                         cudaFuncAttributeMaxDynamicSharedMemorySize, SMEM_TOTAL);
    simreduce_kernel<<<148, 256, SMEM_TOTAL>>>();

    loss_kernel<<<512, 256>>>((float*)d_out);
}

// round 12
// speedup vs baseline: 1.2943x; 1.1107x over previous
#include <cuda_runtime.h>
#include <cuda_fp16.h>

#define NROWS 4096
#define DIM 256
#define EXPSC 14.4269504088896340736f  /* 10 * log2(e) */
#define SQRT_EXPSC 3.7982825381f       /* sqrt(EXPSC) */
#define LN2F 0.69314718056f

// persistent device scratch (no allocations allowed)
// z vectors are L2-normalized AND scaled by SQRT_EXPSC, so any dot product
// of two stored vectors equals EXPSC * cosine_sim directly (exp2-ready).
__device__ __half g_z1[NROWS * DIM];
__device__ __half g_z2[NROWS * DIM];
// 0: rowsum(exp sim12, diag zeroed), 1: colsum(exp sim12, diag zeroed),
// 2: rowsum(exp sim11 masked), 3: rowsum(exp sim22 masked)
__device__ float g_rowsum[4][NROWS];

__device__ __forceinline__ float fast_ex2(float x) {
    float y;
    asm("ex2.approx.f32 %0, %1;" : "=f"(y) : "f"(x));
    return y;
}
__device__ __forceinline__ unsigned ex2h2(unsigned x) {
    unsigned y;
    asm("ex2.approx.f16x2 %0, %1;" : "=r"(y) : "r"(x));
    return y;
}
__device__ __forceinline__ unsigned hadd2u(unsigned a, unsigned b) {
    unsigned d;
    asm("add.rn.f16x2 %0, %1, %2;" : "=r"(d) : "r"(a), "r"(b));
    return d;
}

// ---------------------------------------------------------------------------
// Kernel 1: L2-normalize rows (eps clamp) * SQRT_EXPSC, fp32->fp16;
// zero g_rowsum. One warp per row.
// ---------------------------------------------------------------------------
__global__ void normalize_kernel(const float* __restrict__ x1,
                                 const float* __restrict__ x2) {
    int gt = blockIdx.x * blockDim.x + threadIdx.x;
    if (gt < 4 * NROWS) (&g_rowsum[0][0])[gt] = 0.0f;

    int gw = gt >> 5;
    int lane = threadIdx.x & 31;
    const float* src;
    __half* dst;
    int row;
    if (gw < NROWS) { src = x1; dst = g_z1; row = gw; }
    else            { src = x2; dst = g_z2; row = gw - NROWS; }

    const float4* p = (const float4*)(src + row * DIM);
    float4 a = p[lane];
    float4 b = p[lane + 32];
    float s = a.x*a.x + a.y*a.y + a.z*a.z + a.w*a.w
            + b.x*b.x + b.y*b.y + b.z*b.z + b.w*b.w;
#pragma unroll
    for (int o = 16; o; o >>= 1) s += __shfl_xor_sync(0xffffffffu, s, o);
    float sc = SQRT_EXPSC / fmaxf(sqrtf(s), 1e-8f);

    __half2 h0 = __floats2half2_rn(a.x * sc, a.y * sc);
    __half2 h1 = __floats2half2_rn(a.z * sc, a.w * sc);
    __half2 h2 = __floats2half2_rn(b.x * sc, b.y * sc);
    __half2 h3 = __floats2half2_rn(b.z * sc, b.w * sc);
    uint2 u0 = make_uint2(*(unsigned*)&h0, *(unsigned*)&h1);
    uint2 u1 = make_uint2(*(unsigned*)&h2, *(unsigned*)&h3);
    *(uint2*)(dst + row * DIM + lane * 4) = u0;
    *(uint2*)(dst + row * DIM + 128 + lane * 4) = u1;
}

// ---------------------------------------------------------------------------
// Kernel 2: fused tile-GEMM + exp row/col-reduce. 148 CTAs, 2 warp-groups,
// fp16 in/accumulate, 64x64 warp tiles. MMA outputs are EXPSC*sim directly,
// so the epilogue is just ex2.f16x2 + fp16x2 reductions (no scaling/cvt).
// Group tile = 128x128xK256; B staged in K-halves (32KB, double-buffered per
// group). Diagonal zeroed (exact); loss kernel re-adds exp(10*diag12).
//   CTA 0..73   : sim12 (z1 x z2^T), 1024 tiles.  row->rs[0], col->rs[1].
//   CTA 74..110 : sim11 upper-tri (528 tiles, pair-ordered stripes).
//   CTA 111..147: sim22 upper-tri.   row->target; col->target by symmetry
//                 (diagonal tiles: rowsum only — full tile computed).
// ---------------------------------------------------------------------------
#define SWZA(r, c) (((r) << 9) | ((((c) ^ ((r) & 7))) << 4))          /* A: 512B rows */
#define SWZB(r, c) (((r) << 8) | ((((c) ^ ((r) & 7)) & 15) << 4))     /* B: 256B rows */
#define SMEM_A 0
#define SMEM_B(grp, buf) (65536 + ((grp) * 2 + (buf)) * 32768)
#define SMEM_TOTAL 196608

__device__ __forceinline__ void cp16(unsigned d, const void* s) {
    asm volatile("cp.async.cg.shared.global [%0], [%1], 16;" :: "r"(d), "l"(s));
}
__device__ __forceinline__ void cp_commit() {
    asm volatile("cp.async.commit_group;");
}
template <int n>
__device__ __forceinline__ void cp_wait() {
    asm volatile("cp.async.wait_group %0;" :: "n"(n));
}
__device__ __forceinline__ void ldsm4(unsigned (&r)[4], unsigned addr) {
    asm volatile("ldmatrix.sync.aligned.m8n8.x4.shared.b16 {%0,%1,%2,%3}, [%4];"
                 : "=r"(r[0]), "=r"(r[1]), "=r"(r[2]), "=r"(r[3]) : "r"(addr));
}
__device__ __forceinline__ void mma16816h(unsigned (&d)[2], const unsigned (&a)[4],
                                          unsigned b0, unsigned b1) {
    asm volatile(
        "mma.sync.aligned.m16n8k16.row.col.f16.f16.f16.f16 "
        "{%0,%1}, {%2,%3,%4,%5}, {%6,%7}, {%0,%1};"
        : "+r"(d[0]), "+r"(d[1])
        : "r"(a[0]), "r"(a[1]), "r"(a[2]), "r"(a[3]), "r"(b0), "r"(b1));
}
__device__ __forceinline__ void bar_group(int g) {
    asm volatile("bar.sync %0, 128;" :: "r"(g + 1) : "memory");
}

// B chunk: 128 N-rows x 128 K fp16 = 32KB. 128 threads x 16 cp16.
__device__ __forceinline__ void load_chunk(unsigned sb, const __half* Bp,
                                           int j, int khalf, int gtid) {
#pragma unroll
    for (int it = 0; it < 16; it++) {
        int idx = gtid + it * 128;
        int r = idx >> 4, c = idx & 15;
        cp16(sb + SWZB(r, c), Bp + (j * 128 + r) * DIM + khalf * 128 + c * 8);
    }
    cp_commit();
}

__global__ void __launch_bounds__(256, 1) simreduce_kernel() {
    extern __shared__ __align__(128) char smem[];
    const unsigned sbase = (unsigned)__cvta_generic_to_shared(smem);
    const unsigned sA = sbase + SMEM_A;

    const int tid = threadIdx.x;
    const int bid = blockIdx.x;
    const int wid = tid >> 5;
    const int lane = tid & 31;
    const int group = wid >> 2;      // 0: warps 0-3, 1: warps 4-7
    const int gtid = tid & 127;
    const int wig = wid & 3;         // warp-in-group
    const int mhalf = wig & 1;       // 64 M-rows
    const int nhalf = wig >> 1;      // 64 N-cols

    const unsigned sB0 = sbase + SMEM_B(group, 0);
    const unsigned sB1 = sbase + SMEM_B(group, 1);

    // ---- work decode: matrix + global tile range [g0, g1) over 128-col tiles ----
    int matrix, g0, g1;
    if (bid < 74) {
        matrix = 0;
        g0 = (1024 * bid) / 74;
        g1 = (1024 * (bid + 1)) / 74;
    } else if (bid < 111) {
        int c = bid - 74;
        matrix = 1;
        g0 = (528 * c) / 37;
        g1 = (528 * (c + 1)) / 37;
    } else {
        int c = bid - 111;
        matrix = 2;
        g0 = (528 * c) / 37;
        g1 = (528 * (c + 1)) / 37;
    }

    const __half* Aptr = (matrix == 2) ? g_z2 : g_z1;
    const __half* Bptr = (matrix == 1) ? g_z1 : g_z2;
    const int rowTarget = (matrix == 0) ? 0 : (1 + matrix);
    const int colTarget = (matrix == 0) ? 1 : (1 + matrix);
    const bool symmetric = (matrix != 0);

    const int lrow = lane & 7, quad = lane >> 3;
    int aRow[4];
#pragma unroll
    for (int mi = 0; mi < 4; mi++)
        aRow[mi] = mhalf * 64 + mi * 16 + lrow + (quad & 1) * 8;
    const int aCq = quad >> 1;
    int bRow[4];
#pragma unroll
    for (int pq = 0; pq < 4; pq++)
        bRow[pq] = nhalf * 64 + pq * 16 + lrow + (quad >> 1) * 8;
    const int bCq = quad & 1;

    const int erow = lane >> 2;        // accumulator row within fragment
    const int ecol = (lane & 3) * 2;   // accumulator col within n8

    int g = g0;
    while (g < g1) {
        // ---- segment decode: stripe + local tile range [j0, j0+len) ----
        int stripe, j0, len;
        if (matrix == 0) {
            stripe = g >> 5;
            j0 = g & 31;
            len = min(g1 - g, 32 - j0);
        } else {
            int P = g / 33, o = g % 33;
            int run1 = 32 - P;           // stripe P: tiles j = P..31
            if (o < run1) {
                stripe = P; j0 = P + o;
                len = min(g1 - g, run1 - o);
            } else {                      // stripe 31-P: tiles j = 31-P..31
                stripe = 31 - P;
                int oo = o - run1;
                j0 = (31 - P) + oo;
                len = min(g1 - g, 33 - o);
            }
        }
        const int row0 = stripe * 128;
        const int ntg = (len > group) ? ((len - group + 1) >> 1) : 0;

        __syncthreads();   // both groups done with previous segment's smem

        // ---- prologue: B(t0,k0), A, B(t0,k1) ----
        if (ntg > 0) load_chunk(sB0, Bptr, j0 + group, 0, gtid);
        else         cp_commit();                                  // c1
#pragma unroll
        for (int it = 0; it < 16; it++) {
            int idx = tid + it * 256;
            int r = idx >> 5, c = idx & 31;
            cp16(sA + SWZA(r, c), Aptr + (row0 + r) * DIM + c * 8);
        }
        cp_commit();                                               // c2 (A)
        if (ntg > 0) load_chunk(sB1, Bptr, j0 + group, 1, gtid);
        else         cp_commit();                                  // c3
        cp_wait<1>();
        __syncthreads();     // A fully landed (and c1)

        float part[8];
#pragma unroll
        for (int k = 0; k < 8; k++) part[k] = 0.f;

        for (int t = 0; t < ntg; t++) {
            const int j = j0 + group + 2 * t;
            const bool more = (t + 1 < ntg);

            unsigned acc[4][8][2];
#pragma unroll
            for (int mi = 0; mi < 4; mi++)
#pragma unroll
                for (int ni = 0; ni < 8; ni++) {
                    acc[mi][ni][0] = 0u;
                    acc[mi][ni][1] = 0u;
                }

            // ---- two K-half stages ----
#pragma unroll
            for (int kh = 0; kh < 2; kh++) {
                const unsigned sBj = kh ? sB1 : sB0;
                cp_wait<1>();
                bar_group(group);
#pragma unroll
                for (int ks = 0; ks < 8; ks++) {
                    const int ksg = kh * 8 + ks;
                    unsigned a[4][4];
#pragma unroll
                    for (int mi = 0; mi < 4; mi++) {
                        unsigned addr = sA + (aRow[mi] << 9) +
                                        (((2 * ksg + aCq) ^ (aRow[mi] & 7)) << 4);
                        ldsm4(a[mi], addr);
                    }
                    unsigned b[4][4];
#pragma unroll
                    for (int pq = 0; pq < 4; pq++) {
                        unsigned addr = sBj + (bRow[pq] << 8) +
                                        ((((2 * ks + bCq) ^ (bRow[pq] & 7)) & 15) << 4);
                        ldsm4(b[pq], addr);
                    }
#pragma unroll
                    for (int mi = 0; mi < 4; mi++)
#pragma unroll
                        for (int ni = 0; ni < 8; ni++)
                            mma16816h(acc[mi][ni], a[mi],
                                      b[ni >> 1][(ni & 1) * 2],
                                      b[ni >> 1][(ni & 1) * 2 + 1]);
                }
                bar_group(group);    // group done reading this chunk
                if (more) load_chunk(kh ? sB1 : sB0, Bptr, j + 2, kh, gtid);
                else      cp_commit();
            }

            // ---- epilogue: 2^acc via ex2.f16x2, diag zeroing, fp16x2 sums ----
            const bool maybeDiag = (j == stripe);
            const bool doCol = (!symmetric) || !maybeDiag;

            unsigned colh[8];
#pragma unroll
            for (int ni = 0; ni < 8; ni++) colh[ni] = 0u;

#pragma unroll
            for (int mi = 0; mi < 4; mi++) {
                unsigned E0 = 0u, E1 = 0u;
                int rr0 = row0 + mhalf * 64 + mi * 16 + erow;   // global rows
                int rr1 = rr0 + 8;
#pragma unroll
                for (int ni = 0; ni < 8; ni++) {
                    unsigned e01 = ex2h2(acc[mi][ni][0]);   // cols (cc0, cc0+1), row rr0
                    unsigned e23 = ex2h2(acc[mi][ni][1]);   // cols (cc0, cc0+1), row rr1
                    if (maybeDiag) {
                        int cc0 = j * 128 + nhalf * 64 + ni * 8 + ecol;
                        int cc1 = cc0 + 1;
                        if (rr0 == cc0) e01 &= 0xFFFF0000u;  // zero diagonal (exact)
                        if (rr0 == cc1) e01 &= 0x0000FFFFu;
                        if (rr1 == cc0) e23 &= 0xFFFF0000u;
                        if (rr1 == cc1) e23 &= 0x0000FFFFu;
                    }
                    E0 = hadd2u(E0, e01);
                    E1 = hadd2u(E1, e23);
                    colh[ni] = hadd2u(colh[ni], hadd2u(e01, e23));
                }
                float2 f0 = __half22float2(*(__half2*)&E0);
                float2 f1 = __half22float2(*(__half2*)&E1);
                part[mi * 2 + 0] += f0.x + f0.y;
                part[mi * 2 + 1] += f1.x + f1.y;
            }

            // column partials: fp16x2 xor-shfl over the 8 erow groups, then REDG
            if (doCol) {
                float* ctgt = &g_rowsum[colTarget][j * 128 + nhalf * 64];
#pragma unroll
                for (int ni = 0; ni < 8; ni++) {
                    unsigned v = colh[ni];
                    v = hadd2u(v, __shfl_xor_sync(0xffffffffu, v, 4));
                    v = hadd2u(v, __shfl_xor_sync(0xffffffffu, v, 8));
                    v = hadd2u(v, __shfl_xor_sync(0xffffffffu, v, 16));
                    if (lane < 4) {
                        float2 f = __half22float2(*(__half2*)&v);
                        int col = ni * 8 + lane * 2;
                        atomicAdd(ctgt + col,     f.x);
                        atomicAdd(ctgt + col + 1, f.y);
                    }
                }
            }
        }

        // flush register row partials for this segment's stripe
#pragma unroll
        for (int k = 0; k < 8; k++) {
            part[k] += __shfl_xor_sync(0xffffffffu, part[k], 1);
            part[k] += __shfl_xor_sync(0xffffffffu, part[k], 2);
        }
        if ((lane & 3) == 0) {
#pragma unroll
            for (int mi = 0; mi < 4; mi++) {
                int r = row0 + mhalf * 64 + mi * 16 + erow;
                atomicAdd(&g_rowsum[rowTarget][r],     part[mi * 2 + 0]);
                atomicAdd(&g_rowsum[rowTarget][r + 8], part[mi * 2 + 1]);
            }
        }

        g += len;
    }
}

// ---------------------------------------------------------------------------
// Kernel 3: final losses. One warp per row: exact fp32 diag dot.
// Stored z are scaled by SQRT_EXPSC, so dot = EXPSC * d. Then:
// exp(10 d) = 2^dot;   10 d = dot * ln2.
// row i    : log(rowsum12[i] + rowsum11m[i] + 2^dot) - dot*ln2
// row N+i  : log(rowsum22m[i] + colsum12[i] + 2^dot) - dot*ln2
// ---------------------------------------------------------------------------
__global__ void loss_kernel(float* __restrict__ out) {
    int w = (blockIdx.x * blockDim.x + threadIdx.x) >> 5;
    int lane = threadIdx.x & 31;
    if (w >= NROWS) return;

    const __half2* p1 = (const __half2*)(g_z1 + w * DIM);
    const __half2* p2 = (const __half2*)(g_z2 + w * DIM);
    float d = 0.f;
#pragma unroll
    for (int i = 0; i < 4; i++) {
        float2 a = __half22float2(p1[lane * 4 + i]);
        float2 b = __half22float2(p2[lane * 4 + i]);
        d += a.x * b.x + a.y * b.y;
    }
#pragma unroll
    for (int o = 16; o; o >>= 1) d += __shfl_xor_sync(0xffffffffu, d, o);

    if (lane == 0) {
        float ed = fast_ex2(d);
        float dl = d * LN2F;
        out[w]         = logf(g_rowsum[0][w] + g_rowsum[2][w] + ed) - dl;
        out[NROWS + w] = logf(g_rowsum[3][w] + g_rowsum[1][w] + ed) - dl;
    }
}

extern "C" void kernel_launch(void* const* d_in, const int* in_sizes, int n_in,
                              void* d_out, int out_size) {
    const float* x1 = (const float*)d_in[0];
    const float* x2 = (const float*)d_in[1];

    normalize_kernel<<<1024, 256>>>(x1, x2);

    cudaFuncSetAttribute(simreduce_kernel,
                         cudaFuncAttributeMaxDynamicSharedMemorySize, SMEM_TOTAL);
    simreduce_kernel<<<148, 256, SMEM_TOTAL>>>();

    loss_kernel<<<512, 256>>>((float*)d_out);
}